// round 13
// baseline (speedup 1.0000x reference)
#include <cuda_runtime.h>
#include <math.h>

// ---------------------------------------------------------------------------
// ProteinEmbeddingPooling — R12 structure (80.0us best), single change:
// attn_kernel gets __launch_bounds__(128, 3) -> 170-reg cap, 3 CTAs/SM.
//   q0  = emb[:,0,:] @ Wq^T + bq ; kq = q0 @ Wk ; cb = q0 . bk (in attn)
//   scores[b,s] = scale*(emb[b,s].kq[b] + cb[b])  (mask)
//   pooled[b]   = softmax_s(scores) . emb[b,:,:]   (online softmax, split-S)
//   ctx = pooled @ Wv^T + bv ; h = ctx @ Wo^T + bo ; LN ; ReLU
// ---------------------------------------------------------------------------

#define BB 32
#define SS 1024
#define DD 1280
#define CTAS_PER_B 16
#define WPB 4
#define NCP CTAS_PER_B                   // attn partials per batch
#define RPW (SS / (CTAS_PER_B * WPB))    // 16 rows per warp

// ---- scratch (device globals; no allocation allowed) ----
__device__ float g_q0[BB * DD];
__device__ float g_kq[BB * DD];
__device__ float g_ctx[BB * DD];
__device__ float g_h[BB * DD];
__device__ float g_pm[BB * NCP];
__device__ float g_pl[BB * NCP];
__device__ float g_pacc[(size_t)BB * NCP * DD];      // 2.6 MB
__device__ float g_pooled[BB * DD];

__device__ __forceinline__ void red_add_v4(float* p, float a, float b,
                                           float c, float d)
{
    asm volatile("red.global.add.v4.f32 [%0], {%1, %2, %3, %4};"
                 :: "l"(p), "f"(a), "f"(b), "f"(c), "f"(d) : "memory");
}

// ---------------------------------------------------------------------------
// init: C matrices start at their bias (gemm RED partials accumulate on top)
// ---------------------------------------------------------------------------
__global__ void init_kernel(const float* __restrict__ bq,
                            const float* __restrict__ bv,
                            const float* __restrict__ bo)
{
    int i = blockIdx.x * blockDim.x + threadIdx.x;
    if (i < BB * DD) {
        int n = i % DD;
        g_q0[i]  = bq[n];
        g_kq[i]  = 0.0f;
        g_ctx[i] = bv[n];
        g_h[i]   = bo[n];
    }
}

// ---------------------------------------------------------------------------
// small GEMM: C[32,1280] += A[32,1280] * op(W)   (R4-exact tiling)
//   MODE 0: W [N,K] row-major (C = A.W^T) ; MODE 1: W [K,N] row-major (C = A.W)
//   SRC: 0 = Aext(lda), 1 = g_q0, 2 = g_pooled, 3 = g_ctx (device-resolved)
//   DST: 0 = g_q0, 1 = g_kq, 2 = g_ctx, 3 = g_h
// grid (20, 32). Epilogue: red.global.add.v4.f32 x2 per thread.
// ---------------------------------------------------------------------------
template<int MODE, int SRC, int DST>
__global__ void __launch_bounds__(256) gemm32(const float* __restrict__ Aext,
                                              size_t lda,
                                              const float* __restrict__ W)
{
    constexpr int NT = 64;
    constexpr int KC = 40;

    const float* A = (SRC == 0) ? Aext
                   : (SRC == 1) ? g_q0
                   : (SRC == 2) ? g_pooled
                   :              g_ctx;
    if (SRC != 0) lda = DD;
    float* C = (DST == 0) ? g_q0
             : (DST == 1) ? g_kq
             : (DST == 2) ? g_ctx
             :              g_h;

    __shared__ float As[KC][33];     // [k][m]
    __shared__ float Ws[KC][68];     // [k][n]

    const int tid = threadIdx.x;
    const int n0 = blockIdx.x * NT;
    const int k0 = blockIdx.y * KC;
    const int k04 = k0 >> 2;

    const float4* A4 = reinterpret_cast<const float4*>(A);
    const size_t lda4 = lda >> 2;
#pragma unroll
    for (int i = 0; i < 2; i++) {
        int f = tid + i * 256;
        if (f < 320) {
            int m = f / 10, kc4 = f % 10;
            float4 v = A4[(size_t)m * lda4 + k04 + kc4];
            As[kc4 * 4 + 0][m] = v.x;
            As[kc4 * 4 + 1][m] = v.y;
            As[kc4 * 4 + 2][m] = v.z;
            As[kc4 * 4 + 3][m] = v.w;
        }
    }

    const float4* W4 = reinterpret_cast<const float4*>(W);
    if (MODE == 1) {
#pragma unroll
        for (int i = 0; i < 3; i++) {
            int f = tid + i * 256;
            if (f < 640) {
                int kr = f >> 4, nc = f & 15;
                float4 v = W4[(size_t)(k0 + kr) * (DD / 4) + (n0 >> 2) + nc];
                reinterpret_cast<float4*>(&Ws[kr][0])[nc] = v;
            }
        }
    } else {
#pragma unroll
        for (int i = 0; i < 3; i++) {
            int f = tid + i * 256;
            if (f < 640) {
                int n = f / 10, kc4 = f % 10;
                float4 v = W4[(size_t)(n0 + n) * (DD / 4) + k04 + kc4];
                Ws[kc4 * 4 + 0][n] = v.x;
                Ws[kc4 * 4 + 1][n] = v.y;
                Ws[kc4 * 4 + 2][n] = v.z;
                Ws[kc4 * 4 + 3][n] = v.w;
            }
        }
    }
    __syncthreads();

    const int tx = tid & 15;
    const int ty = tid >> 4;

    float acc0[4] = {}, acc1[4] = {};
#pragma unroll 8
    for (int k = 0; k < KC; k++) {
        const float a0 = As[k][ty];
        const float a1 = As[k][ty + 16];
        const float4 w = reinterpret_cast<const float4*>(&Ws[k][0])[tx];
        acc0[0] = fmaf(a0, w.x, acc0[0]);
        acc0[1] = fmaf(a0, w.y, acc0[1]);
        acc0[2] = fmaf(a0, w.z, acc0[2]);
        acc0[3] = fmaf(a0, w.w, acc0[3]);
        acc1[0] = fmaf(a1, w.x, acc1[0]);
        acc1[1] = fmaf(a1, w.y, acc1[1]);
        acc1[2] = fmaf(a1, w.z, acc1[2]);
        acc1[3] = fmaf(a1, w.w, acc1[3]);
    }

    red_add_v4(&C[(size_t)ty * DD + n0 + tx * 4],
               acc0[0], acc0[1], acc0[2], acc0[3]);
    red_add_v4(&C[(size_t)(ty + 16) * DD + n0 + tx * 4],
               acc1[0], acc1[1], acc1[2], acc1[3]);
}

// ---------------------------------------------------------------------------
// attention + pooling — R4 loop, NOW with (128, 3) bounds (170-reg cap).
// grid 512 (32 b x 16 CTAs), block 128 (4 warps x 16 rows), manual prefetch.
// ---------------------------------------------------------------------------
__global__ void __launch_bounds__(128, 3) attn_kernel(
    const float* __restrict__ emb,
    const int* __restrict__ mask,
    const float* __restrict__ bk,
    float scale)
{
    __shared__ float skq[DD];
    __shared__ float4 sacc[WPB][DD / 4];
    __shared__ float sm[WPB], sl[WPB], scb;

    const int b = blockIdx.x / CTAS_PER_B;
    const int cta = blockIdx.x % CTAS_PER_B;
    const int tid = threadIdx.x;
    const int warp = tid >> 5;
    const int lane = tid & 31;
    const int split = cta * WPB + warp;
    const int s0 = split * RPW;

    {
        const float4* src = reinterpret_cast<const float4*>(g_kq + b * DD);
        float4* dst = reinterpret_cast<float4*>(skq);
        for (int i = tid; i < DD / 4; i += 128) dst[i] = src[i];
    }
    if (warp == 0) {
        const float4* q04 = reinterpret_cast<const float4*>(g_q0 + b * DD);
        const float4* bk4 = reinterpret_cast<const float4*>(bk);
        float p = 0.0f;
#pragma unroll
        for (int c = 0; c < 10; c++) {
            const float4 q = q04[c * 32 + lane];
            const float4 k = bk4[c * 32 + lane];
            p = fmaf(q.x, k.x, p); p = fmaf(q.y, k.y, p);
            p = fmaf(q.z, k.z, p); p = fmaf(q.w, k.w, p);
        }
#pragma unroll
        for (int off = 16; off > 0; off >>= 1)
            p += __shfl_xor_sync(0xffffffffu, p, off);
        if (lane == 0) scb = p;
    }

    const float* base = emb + (size_t)b * SS * DD;
    float4 x[10];
    {
        const float4* row = reinterpret_cast<const float4*>(base + (size_t)s0 * DD);
#pragma unroll
        for (int c = 0; c < 10; c++) x[c] = row[c * 32 + lane];
    }
    const int* mrow = mask + b * SS;

    __syncthreads();
    const float cb = scb;

    float m = -INFINITY, l = 0.0f;
    float4 acc[10];
#pragma unroll
    for (int c = 0; c < 10; c++) acc[c] = make_float4(0.f, 0.f, 0.f, 0.f);

#pragma unroll 4
    for (int r = 0; r < RPW; r++) {
        const int s = s0 + r;
        const int mk = mrow[s];

        float4 y[10];
        {
            const int rn = (r + 1 < RPW) ? r + 1 : r;
            const float4* nrow =
                reinterpret_cast<const float4*>(base + (size_t)(s0 + rn) * DD);
#pragma unroll
            for (int c = 0; c < 10; c++) y[c] = nrow[c * 32 + lane];
        }

        float p = 0.0f;
        const float4* kq4 = reinterpret_cast<const float4*>(skq);
#pragma unroll
        for (int c = 0; c < 10; c++) {
            const float4 k = kq4[c * 32 + lane];
            p = fmaf(x[c].x, k.x, p);
            p = fmaf(x[c].y, k.y, p);
            p = fmaf(x[c].z, k.z, p);
            p = fmaf(x[c].w, k.w, p);
        }
#pragma unroll
        for (int off = 16; off > 0; off >>= 1)
            p += __shfl_xor_sync(0xffffffffu, p, off);

        float score = (p + cb) * scale;
        if (mk == 0) score = -1e9f;

        const float mn = fmaxf(m, score);
        if (mn > m) {
            const float fac = __expf(m - mn);
            l *= fac;
#pragma unroll
            for (int c = 0; c < 10; c++) {
                acc[c].x *= fac; acc[c].y *= fac;
                acc[c].z *= fac; acc[c].w *= fac;
            }
            m = mn;
        }
        const float w = __expf(score - m);
        l += w;
#pragma unroll
        for (int c = 0; c < 10; c++) {
            acc[c].x = fmaf(w, x[c].x, acc[c].x);
            acc[c].y = fmaf(w, x[c].y, acc[c].y);
            acc[c].z = fmaf(w, x[c].z, acc[c].z);
            acc[c].w = fmaf(w, x[c].w, acc[c].w);
        }
#pragma unroll
        for (int c = 0; c < 10; c++) x[c] = y[c];
    }

#pragma unroll
    for (int c = 0; c < 10; c++) sacc[warp][c * 32 + lane] = acc[c];
    if (lane == 0) { sm[warp] = m; sl[warp] = l; }
    __syncthreads();

    const float M = fmaxf(fmaxf(sm[0], sm[1]), fmaxf(sm[2], sm[3]));
    const float f0 = __expf(sm[0] - M), f1 = __expf(sm[1] - M);
    const float f2 = __expf(sm[2] - M), f3 = __expf(sm[3] - M);
    const float L = f0 * sl[0] + f1 * sl[1] + f2 * sl[2] + f3 * sl[3];

    const int pidx = b * NCP + cta;
    float4* pa = reinterpret_cast<float4*>(g_pacc + (size_t)pidx * DD);
#pragma unroll
    for (int i = 0; i < 3; i++) {
        const int idx = tid + i * 128;
        if (idx < DD / 4) {
            const float4 a0 = sacc[0][idx], a1 = sacc[1][idx];
            const float4 a2 = sacc[2][idx], a3 = sacc[3][idx];
            float4 s;
            s.x = fmaf(f0, a0.x, fmaf(f1, a1.x, fmaf(f2, a2.x, f3 * a3.x)));
            s.y = fmaf(f0, a0.y, fmaf(f1, a1.y, fmaf(f2, a2.y, f3 * a3.y)));
            s.z = fmaf(f0, a0.z, fmaf(f1, a1.z, fmaf(f2, a2.z, f3 * a3.z)));
            s.w = fmaf(f0, a0.w, fmaf(f1, a1.w, fmaf(f2, a2.w, f3 * a3.w)));
            pa[idx] = s;
        }
    }
    if (tid == 0) { g_pm[pidx] = M; g_pl[pidx] = L; }
}

// ---------------------------------------------------------------------------
// combine 16 CTA-partials -> pooled[b,:]. grid 32, block 320.
// ---------------------------------------------------------------------------
__global__ void __launch_bounds__(320) combine_kernel()
{
    const int b = blockIdx.x;
    __shared__ float fs[NCP], ls[NCP];

    if (threadIdx.x < NCP) {
        float M = -INFINITY;
#pragma unroll
        for (int p = 0; p < NCP; p++) M = fmaxf(M, g_pm[b * NCP + p]);
        const float f = __expf(g_pm[b * NCP + threadIdx.x] - M);
        fs[threadIdx.x] = f;
        ls[threadIdx.x] = f * g_pl[b * NCP + threadIdx.x];
    }
    __syncthreads();

    float L = 0.0f;
#pragma unroll
    for (int p = 0; p < NCP; p++) L += ls[p];
    const float invL = 1.0f / L;

    const int d4 = threadIdx.x;   // 0..319
    float4 sum = make_float4(0.f, 0.f, 0.f, 0.f);
#pragma unroll
    for (int p = 0; p < NCP; p++) {
        const float f = fs[p];
        const float4 a = reinterpret_cast<const float4*>(
            g_pacc + (size_t)(b * NCP + p) * DD)[d4];
        sum.x = fmaf(f, a.x, sum.x);
        sum.y = fmaf(f, a.y, sum.y);
        sum.z = fmaf(f, a.z, sum.z);
        sum.w = fmaf(f, a.w, sum.w);
    }
    reinterpret_cast<float4*>(g_pooled + b * DD)[d4] =
        make_float4(sum.x * invL, sum.y * invL, sum.z * invL, sum.w * invL);
}

// ---------------------------------------------------------------------------
// LayerNorm + ReLU on g_h[32,1280] -> out. grid 32, block 320 (shuffle reduce).
// ---------------------------------------------------------------------------
__global__ void __launch_bounds__(320) ln_kernel(const float* __restrict__ gamma,
                                                 const float* __restrict__ beta,
                                                 float* __restrict__ out)
{
    const int b = blockIdx.x, tid = threadIdx.x;   // tid = float4 idx
    const int warp = tid >> 5, lane = tid & 31;

    const float4 s = reinterpret_cast<const float4*>(g_h)[b * (DD / 4) + tid];

    float sum = s.x + s.y + s.z + s.w;
    float sq  = s.x * s.x + s.y * s.y + s.z * s.z + s.w * s.w;
#pragma unroll
    for (int off = 16; off > 0; off >>= 1) {
        sum += __shfl_xor_sync(0xffffffffu, sum, off);
        sq  += __shfl_xor_sync(0xffffffffu, sq,  off);
    }
    __shared__ float rs[10], rq[10];
    __shared__ float smu, sinv;
    if (lane == 0) { rs[warp] = sum; rq[warp] = sq; }
    __syncthreads();
    if (tid == 0) {
        float S = 0.f, Q = 0.f;
#pragma unroll
        for (int w = 0; w < 10; w++) { S += rs[w]; Q += rq[w]; }
        const float mu = S * (1.0f / DD);
        float var = Q * (1.0f / DD) - mu * mu;
        var = fmaxf(var, 0.0f);
        smu = mu;
        sinv = rsqrtf(var + 1e-5f);
    }
    __syncthreads();
    const float mu = smu, inv = sinv;

    const float4 g  = reinterpret_cast<const float4*>(gamma)[tid];
    const float4 be = reinterpret_cast<const float4*>(beta)[tid];
    float4 o;
    o.x = fmaxf(fmaf((s.x - mu) * inv, g.x, be.x), 0.0f);
    o.y = fmaxf(fmaf((s.y - mu) * inv, g.y, be.y), 0.0f);
    o.z = fmaxf(fmaf((s.z - mu) * inv, g.z, be.z), 0.0f);
    o.w = fmaxf(fmaf((s.w - mu) * inv, g.w, be.w), 0.0f);
    reinterpret_cast<float4*>(out)[b * (DD / 4) + tid] = o;
}

// ---------------------------------------------------------------------------
extern "C" void kernel_launch(void* const* d_in, const int* in_sizes, int n_in,
                              void* d_out, int out_size)
{
    (void)in_sizes; (void)n_in; (void)out_size;

    const float* emb   = (const float*)d_in[0];
    const int*   mask  = (const int*)d_in[1];
    const float* Wq    = (const float*)d_in[2];
    const float* bq    = (const float*)d_in[3];
    const float* Wk    = (const float*)d_in[4];
    const float* bk    = (const float*)d_in[5];
    const float* Wv    = (const float*)d_in[6];
    const float* bv    = (const float*)d_in[7];
    const float* Wo    = (const float*)d_in[8];
    const float* bo    = (const float*)d_in[9];
    const float* gamma = (const float*)d_in[10];
    const float* beta  = (const float*)d_in[11];
    float* out = (float*)d_out;

    const float scale = 1.0f / sqrtf((float)DD);
    const dim3 ggrid(DD / 64, 32);   // 20 n-tiles x 32 k-splits = 640 CTAs

    init_kernel<<<(BB * DD + 255) / 256, 256>>>(bq, bv, bo);
    gemm32<0, 0, 0><<<ggrid, 256>>>(emb, (size_t)SS * DD, Wq);     // q0
    gemm32<1, 1, 1><<<ggrid, 256>>>(nullptr, 0, Wk);               // kq = q0@Wk
    attn_kernel<<<BB * CTAS_PER_B, 128>>>(emb, mask, bk, scale);   // pool
    combine_kernel<<<BB, 320>>>();
    gemm32<0, 2, 2><<<ggrid, 256>>>(nullptr, 0, Wv);               // ctx
    gemm32<0, 3, 3><<<ggrid, 256>>>(nullptr, 0, Wo);               // h
    ln_kernel<<<BB, 320>>>(gamma, beta, out);
}

// round 14
// speedup vs baseline: 1.2416x; 1.2416x over previous
#include <cuda_runtime.h>
#include <math.h>

// ---------------------------------------------------------------------------
// ProteinEmbeddingPooling — R12 structure (80.0us best):
//   attn reverted to R12-exact (255 regs, 2 CTAs/SM — proven optimum).
//   gemm32 compute upgraded: 4m x 4n register tile, 128 threads
//   (2 B of LDS per FMA instead of 3 — smem-crossbar was the GEMM limiter).
// ---------------------------------------------------------------------------

#define BB 32
#define SS 1024
#define DD 1280
#define CTAS_PER_B 16
#define WPB 4
#define NCP CTAS_PER_B                   // attn partials per batch
#define RPW (SS / (CTAS_PER_B * WPB))    // 16 rows per warp

// ---- scratch (device globals; no allocation allowed) ----
__device__ float g_q0[BB * DD];
__device__ float g_kq[BB * DD];
__device__ float g_ctx[BB * DD];
__device__ float g_h[BB * DD];
__device__ float g_pm[BB * NCP];
__device__ float g_pl[BB * NCP];
__device__ float g_pacc[(size_t)BB * NCP * DD];      // 2.6 MB
__device__ float g_pooled[BB * DD];

__device__ __forceinline__ void red_add_v4(float* p, float a, float b,
                                           float c, float d)
{
    asm volatile("red.global.add.v4.f32 [%0], {%1, %2, %3, %4};"
                 :: "l"(p), "f"(a), "f"(b), "f"(c), "f"(d) : "memory");
}

// ---------------------------------------------------------------------------
// init: C matrices start at their bias (gemm RED partials accumulate on top)
// ---------------------------------------------------------------------------
__global__ void init_kernel(const float* __restrict__ bq,
                            const float* __restrict__ bv,
                            const float* __restrict__ bo)
{
    int i = blockIdx.x * blockDim.x + threadIdx.x;
    if (i < BB * DD) {
        int n = i % DD;
        g_q0[i]  = bq[n];
        g_kq[i]  = 0.0f;
        g_ctx[i] = bv[n];
        g_h[i]   = bo[n];
    }
}

// ---------------------------------------------------------------------------
// small GEMM: C[32,1280] += A[32,1280] * op(W)
//   MODE 0: W [N,K] row-major (C = A.W^T) ; MODE 1: W [K,N] row-major (C = A.W)
//   SRC: 0 = Aext(lda), 1 = g_q0, 2 = g_pooled, 3 = g_ctx (device-resolved)
//   DST: 0 = g_q0, 1 = g_kq, 2 = g_ctx, 3 = g_h
// grid (20, 32), block 128. 4m x 4n register tile (16 outputs/thread).
// Per k per thread: 16B As + 16B Ws for 16 FMA (2 B/FMA).
// Epilogue: red.global.add.v4.f32 x4 per thread.
// ---------------------------------------------------------------------------
template<int MODE, int SRC, int DST>
__global__ void __launch_bounds__(128) gemm32(const float* __restrict__ Aext,
                                              size_t lda,
                                              const float* __restrict__ W)
{
    constexpr int NT = 64;
    constexpr int KC = 40;

    const float* A = (SRC == 0) ? Aext
                   : (SRC == 1) ? g_q0
                   : (SRC == 2) ? g_pooled
                   :              g_ctx;
    if (SRC != 0) lda = DD;
    float* C = (DST == 0) ? g_q0
             : (DST == 1) ? g_kq
             : (DST == 2) ? g_ctx
             :              g_h;

    __shared__ float As[KC][33];     // [k][m]
    __shared__ float Ws[KC][68];     // [k][n]

    const int tid = threadIdx.x;     // 0..127
    const int n0 = blockIdx.x * NT;
    const int k0 = blockIdx.y * KC;
    const int k04 = k0 >> 2;

    // ---- A tile (32 x 40) via float4 (320 float4, 2.5/thread) ----
    const float4* A4 = reinterpret_cast<const float4*>(A);
    const size_t lda4 = lda >> 2;
#pragma unroll
    for (int i = 0; i < 3; i++) {
        int f = tid + i * 128;
        if (f < 320) {
            int m = f / 10, kc4 = f % 10;
            float4 v = A4[(size_t)m * lda4 + k04 + kc4];
            As[kc4 * 4 + 0][m] = v.x;
            As[kc4 * 4 + 1][m] = v.y;
            As[kc4 * 4 + 2][m] = v.z;
            As[kc4 * 4 + 3][m] = v.w;
        }
    }

    // ---- W tile (640 float4, 5/thread) -> Ws[k][n] ----
    const float4* W4 = reinterpret_cast<const float4*>(W);
    if (MODE == 1) {
#pragma unroll
        for (int i = 0; i < 5; i++) {
            int f = tid + i * 128;       // 0..639
            int kr = f >> 4, nc = f & 15;
            float4 v = W4[(size_t)(k0 + kr) * (DD / 4) + (n0 >> 2) + nc];
            reinterpret_cast<float4*>(&Ws[kr][0])[nc] = v;
        }
    } else {
#pragma unroll
        for (int i = 0; i < 5; i++) {
            int f = tid + i * 128;
            int n = f / 10, kc4 = f % 10;
            float4 v = W4[(size_t)(n0 + n) * (DD / 4) + k04 + kc4];
            Ws[kc4 * 4 + 0][n] = v.x;
            Ws[kc4 * 4 + 1][n] = v.y;
            Ws[kc4 * 4 + 2][n] = v.z;
            Ws[kc4 * 4 + 3][n] = v.w;
        }
    }
    __syncthreads();

    // ---- compute: m {ty, ty+8, ty+16, ty+24} x n {tx*4 .. tx*4+3} ----
    const int tx = tid & 15;
    const int ty = tid >> 4;             // 0..7

    float acc[4][4] = {};
#pragma unroll 8
    for (int k = 0; k < KC; k++) {
        float a[4];
#pragma unroll
        for (int i = 0; i < 4; i++) a[i] = As[k][ty + 8 * i];
        const float4 w = reinterpret_cast<const float4*>(&Ws[k][0])[tx];
#pragma unroll
        for (int i = 0; i < 4; i++) {
            acc[i][0] = fmaf(a[i], w.x, acc[i][0]);
            acc[i][1] = fmaf(a[i], w.y, acc[i][1]);
            acc[i][2] = fmaf(a[i], w.z, acc[i][2]);
            acc[i][3] = fmaf(a[i], w.w, acc[i][3]);
        }
    }

#pragma unroll
    for (int i = 0; i < 4; i++)
        red_add_v4(&C[(size_t)(ty + 8 * i) * DD + n0 + tx * 4],
                   acc[i][0], acc[i][1], acc[i][2], acc[i][3]);
}

// ---------------------------------------------------------------------------
// attention + pooling — R12-exact (empirical best: 36.5us). FROZEN.
// grid 512 (32 b x 16 CTAs), block 128 (4 warps x 16 rows), manual prefetch.
// ---------------------------------------------------------------------------
__global__ void __launch_bounds__(128) attn_kernel(const float* __restrict__ emb,
                                                   const int* __restrict__ mask,
                                                   const float* __restrict__ bk,
                                                   float scale)
{
    __shared__ float skq[DD];
    __shared__ float4 sacc[WPB][DD / 4];
    __shared__ float sm[WPB], sl[WPB], scb;

    const int b = blockIdx.x / CTAS_PER_B;
    const int cta = blockIdx.x % CTAS_PER_B;
    const int tid = threadIdx.x;
    const int warp = tid >> 5;
    const int lane = tid & 31;
    const int split = cta * WPB + warp;
    const int s0 = split * RPW;

    {
        const float4* src = reinterpret_cast<const float4*>(g_kq + b * DD);
        float4* dst = reinterpret_cast<float4*>(skq);
        for (int i = tid; i < DD / 4; i += 128) dst[i] = src[i];
    }
    if (warp == 0) {
        const float4* q04 = reinterpret_cast<const float4*>(g_q0 + b * DD);
        const float4* bk4 = reinterpret_cast<const float4*>(bk);
        float p = 0.0f;
#pragma unroll
        for (int c = 0; c < 10; c++) {
            const float4 q = q04[c * 32 + lane];
            const float4 k = bk4[c * 32 + lane];
            p = fmaf(q.x, k.x, p); p = fmaf(q.y, k.y, p);
            p = fmaf(q.z, k.z, p); p = fmaf(q.w, k.w, p);
        }
#pragma unroll
        for (int off = 16; off > 0; off >>= 1)
            p += __shfl_xor_sync(0xffffffffu, p, off);
        if (lane == 0) scb = p;
    }

    const float* base = emb + (size_t)b * SS * DD;
    float4 x[10];
    {
        const float4* row = reinterpret_cast<const float4*>(base + (size_t)s0 * DD);
#pragma unroll
        for (int c = 0; c < 10; c++) x[c] = row[c * 32 + lane];
    }
    const int* mrow = mask + b * SS;

    __syncthreads();
    const float cb = scb;

    float m = -INFINITY, l = 0.0f;
    float4 acc[10];
#pragma unroll
    for (int c = 0; c < 10; c++) acc[c] = make_float4(0.f, 0.f, 0.f, 0.f);

#pragma unroll 4
    for (int r = 0; r < RPW; r++) {
        const int s = s0 + r;
        const int mk = mrow[s];

        float4 y[10];
        {
            const int rn = (r + 1 < RPW) ? r + 1 : r;
            const float4* nrow =
                reinterpret_cast<const float4*>(base + (size_t)(s0 + rn) * DD);
#pragma unroll
            for (int c = 0; c < 10; c++) y[c] = nrow[c * 32 + lane];
        }

        float p = 0.0f;
        const float4* kq4 = reinterpret_cast<const float4*>(skq);
#pragma unroll
        for (int c = 0; c < 10; c++) {
            const float4 k = kq4[c * 32 + lane];
            p = fmaf(x[c].x, k.x, p);
            p = fmaf(x[c].y, k.y, p);
            p = fmaf(x[c].z, k.z, p);
            p = fmaf(x[c].w, k.w, p);
        }
#pragma unroll
        for (int off = 16; off > 0; off >>= 1)
            p += __shfl_xor_sync(0xffffffffu, p, off);

        float score = (p + cb) * scale;
        if (mk == 0) score = -1e9f;

        const float mn = fmaxf(m, score);
        if (mn > m) {
            const float fac = __expf(m - mn);
            l *= fac;
#pragma unroll
            for (int c = 0; c < 10; c++) {
                acc[c].x *= fac; acc[c].y *= fac;
                acc[c].z *= fac; acc[c].w *= fac;
            }
            m = mn;
        }
        const float w = __expf(score - m);
        l += w;
#pragma unroll
        for (int c = 0; c < 10; c++) {
            acc[c].x = fmaf(w, x[c].x, acc[c].x);
            acc[c].y = fmaf(w, x[c].y, acc[c].y);
            acc[c].z = fmaf(w, x[c].z, acc[c].z);
            acc[c].w = fmaf(w, x[c].w, acc[c].w);
        }
#pragma unroll
        for (int c = 0; c < 10; c++) x[c] = y[c];
    }

#pragma unroll
    for (int c = 0; c < 10; c++) sacc[warp][c * 32 + lane] = acc[c];
    if (lane == 0) { sm[warp] = m; sl[warp] = l; }
    __syncthreads();

    const float M = fmaxf(fmaxf(sm[0], sm[1]), fmaxf(sm[2], sm[3]));
    const float f0 = __expf(sm[0] - M), f1 = __expf(sm[1] - M);
    const float f2 = __expf(sm[2] - M), f3 = __expf(sm[3] - M);
    const float L = f0 * sl[0] + f1 * sl[1] + f2 * sl[2] + f3 * sl[3];

    const int pidx = b * NCP + cta;
    float4* pa = reinterpret_cast<float4*>(g_pacc + (size_t)pidx * DD);
#pragma unroll
    for (int i = 0; i < 3; i++) {
        const int idx = tid + i * 128;
        if (idx < DD / 4) {
            const float4 a0 = sacc[0][idx], a1 = sacc[1][idx];
            const float4 a2 = sacc[2][idx], a3 = sacc[3][idx];
            float4 s;
            s.x = fmaf(f0, a0.x, fmaf(f1, a1.x, fmaf(f2, a2.x, f3 * a3.x)));
            s.y = fmaf(f0, a0.y, fmaf(f1, a1.y, fmaf(f2, a2.y, f3 * a3.y)));
            s.z = fmaf(f0, a0.z, fmaf(f1, a1.z, fmaf(f2, a2.z, f3 * a3.z)));
            s.w = fmaf(f0, a0.w, fmaf(f1, a1.w, fmaf(f2, a2.w, f3 * a3.w)));
            pa[idx] = s;
        }
    }
    if (tid == 0) { g_pm[pidx] = M; g_pl[pidx] = L; }
}

// ---------------------------------------------------------------------------
// combine 16 CTA-partials -> pooled[b,:]. grid 32, block 320.
// ---------------------------------------------------------------------------
__global__ void __launch_bounds__(320) combine_kernel()
{
    const int b = blockIdx.x;
    __shared__ float fs[NCP], ls[NCP];

    if (threadIdx.x < NCP) {
        float M = -INFINITY;
#pragma unroll
        for (int p = 0; p < NCP; p++) M = fmaxf(M, g_pm[b * NCP + p]);
        const float f = __expf(g_pm[b * NCP + threadIdx.x] - M);
        fs[threadIdx.x] = f;
        ls[threadIdx.x] = f * g_pl[b * NCP + threadIdx.x];
    }
    __syncthreads();

    float L = 0.0f;
#pragma unroll
    for (int p = 0; p < NCP; p++) L += ls[p];
    const float invL = 1.0f / L;

    const int d4 = threadIdx.x;   // 0..319
    float4 sum = make_float4(0.f, 0.f, 0.f, 0.f);
#pragma unroll
    for (int p = 0; p < NCP; p++) {
        const float f = fs[p];
        const float4 a = reinterpret_cast<const float4*>(
            g_pacc + (size_t)(b * NCP + p) * DD)[d4];
        sum.x = fmaf(f, a.x, sum.x);
        sum.y = fmaf(f, a.y, sum.y);
        sum.z = fmaf(f, a.z, sum.z);
        sum.w = fmaf(f, a.w, sum.w);
    }
    reinterpret_cast<float4*>(g_pooled + b * DD)[d4] =
        make_float4(sum.x * invL, sum.y * invL, sum.z * invL, sum.w * invL);
}

// ---------------------------------------------------------------------------
// LayerNorm + ReLU on g_h[32,1280] -> out. grid 32, block 320 (shuffle reduce).
// ---------------------------------------------------------------------------
__global__ void __launch_bounds__(320) ln_kernel(const float* __restrict__ gamma,
                                                 const float* __restrict__ beta,
                                                 float* __restrict__ out)
{
    const int b = blockIdx.x, tid = threadIdx.x;   // tid = float4 idx
    const int warp = tid >> 5, lane = tid & 31;

    const float4 s = reinterpret_cast<const float4*>(g_h)[b * (DD / 4) + tid];

    float sum = s.x + s.y + s.z + s.w;
    float sq  = s.x * s.x + s.y * s.y + s.z * s.z + s.w * s.w;
#pragma unroll
    for (int off = 16; off > 0; off >>= 1) {
        sum += __shfl_xor_sync(0xffffffffu, sum, off);
        sq  += __shfl_xor_sync(0xffffffffu, sq,  off);
    }
    __shared__ float rs[10], rq[10];
    __shared__ float smu, sinv;
    if (lane == 0) { rs[warp] = sum; rq[warp] = sq; }
    __syncthreads();
    if (tid == 0) {
        float S = 0.f, Q = 0.f;
#pragma unroll
        for (int w = 0; w < 10; w++) { S += rs[w]; Q += rq[w]; }
        const float mu = S * (1.0f / DD);
        float var = Q * (1.0f / DD) - mu * mu;
        var = fmaxf(var, 0.0f);
        smu = mu;
        sinv = rsqrtf(var + 1e-5f);
    }
    __syncthreads();
    const float mu = smu, inv = sinv;

    const float4 g  = reinterpret_cast<const float4*>(gamma)[tid];
    const float4 be = reinterpret_cast<const float4*>(beta)[tid];
    float4 o;
    o.x = fmaxf(fmaf((s.x - mu) * inv, g.x, be.x), 0.0f);
    o.y = fmaxf(fmaf((s.y - mu) * inv, g.y, be.y), 0.0f);
    o.z = fmaxf(fmaf((s.z - mu) * inv, g.z, be.z), 0.0f);
    o.w = fmaxf(fmaf((s.w - mu) * inv, g.w, be.w), 0.0f);
    reinterpret_cast<float4*>(out)[b * (DD / 4) + tid] = o;
}

// ---------------------------------------------------------------------------
extern "C" void kernel_launch(void* const* d_in, const int* in_sizes, int n_in,
                              void* d_out, int out_size)
{
    (void)in_sizes; (void)n_in; (void)out_size;

    const float* emb   = (const float*)d_in[0];
    const int*   mask  = (const int*)d_in[1];
    const float* Wq    = (const float*)d_in[2];
    const float* bq    = (const float*)d_in[3];
    const float* Wk    = (const float*)d_in[4];
    const float* bk    = (const float*)d_in[5];
    const float* Wv    = (const float*)d_in[6];
    const float* bv    = (const float*)d_in[7];
    const float* Wo    = (const float*)d_in[8];
    const float* bo    = (const float*)d_in[9];
    const float* gamma = (const float*)d_in[10];
    const float* beta  = (const float*)d_in[11];
    float* out = (float*)d_out;

    const float scale = 1.0f / sqrtf((float)DD);
    const dim3 ggrid(DD / 64, 32);   // 20 n-tiles x 32 k-splits = 640 CTAs

    init_kernel<<<(BB * DD + 255) / 256, 256>>>(bq, bv, bo);
    gemm32<0, 0, 0><<<ggrid, 128>>>(emb, (size_t)SS * DD, Wq);     // q0
    gemm32<1, 1, 1><<<ggrid, 128>>>(nullptr, 0, Wk);               // kq = q0@Wk
    attn_kernel<<<BB * CTAS_PER_B, 128>>>(emb, mask, bk, scale);   // pool
    combine_kernel<<<BB, 320>>>();
    gemm32<0, 2, 2><<<ggrid, 128>>>(nullptr, 0, Wv);               // ctx
    gemm32<0, 3, 3><<<ggrid, 128>>>(nullptr, 0, Wo);               // h
    ln_kernel<<<BB, 320>>>(gamma, beta, out);
}